// round 2
// baseline (speedup 1.0000x reference)
#include <cuda_runtime.h>
#include <cstdint>

#define NSEQ 2048
#define DD 512
#define VV 512
#define CL 16          // cluster size (nonportable)

// ---------------- device scratch (no allocations allowed) ----------------
static __device__ float g_X [NSEQ * DD];
static __device__ float g_XW[NSEQ * DD];
static __device__ float g_H [NSEQ * DD];
static __device__ float g_O [NSEQ * VV];
static __device__ int   g_is64;

// ---------------- helpers ----------------
__device__ __forceinline__ uint32_t ctarank() {
    uint32_t r; asm("mov.u32 %0, %%cluster_ctarank;" : "=r"(r)); return r;
}
__device__ __forceinline__ uint32_t s2u(const void* p) {
    uint32_t a;
    asm("{ .reg .u64 t; cvta.to.shared.u64 t, %1; cvt.u32.u64 %0, t; }" : "=r"(a) : "l"(p));
    return a;
}
__device__ __forceinline__ void dsmem_st(uint32_t laddr, uint32_t trank, float v) {
    uint32_t r;
    asm volatile("mapa.shared::cluster.u32 %0, %1, %2;" : "=r"(r) : "r"(laddr), "r"(trank));
    asm volatile("st.shared::cluster.f32 [%0], %1;" :: "r"(r), "f"(v) : "memory");
}
__device__ __forceinline__ void cl_arrive() {
    asm volatile("barrier.cluster.arrive.aligned;" ::: "memory");
}
__device__ __forceinline__ void cl_wait() {
    asm volatile("barrier.cluster.wait.aligned;" ::: "memory");
}
__device__ __forceinline__ float ex2f_(float x) {
    float y; asm("ex2.approx.f32 %0, %1;" : "=f"(y) : "f"(x)); return y;
}
__device__ __forceinline__ float lg2f_(float x) {
    float y; asm("lg2.approx.f32 %0, %1;" : "=f"(y) : "f"(x)); return y;
}
__device__ __forceinline__ float rcpf_(float x) {
    float y; asm("rcp.approx.f32 %0, %1;" : "=f"(y) : "f"(x)); return y;
}
// tanh(x) = 1 - 2/(exp(2x)+1), via ex2 + rcp (2 MUFU ops, ~1e-6 accurate)
__device__ __forceinline__ float tanh_ex2(float x) {
    float t = ex2f_(2.8853900817779268f * x);   // e^(2x)
    float r = rcpf_(t + 1.0f);
    return fmaf(-2.0f, r, 1.0f);
}

// ---------------- int64-vs-int32 index detection ----------------
__global__ void detect_kernel(const int* __restrict__ w) {
    __shared__ int any;
    if (threadIdx.x == 0) any = 0;
    __syncthreads();
    int acc = 0;
    for (int i = threadIdx.x; i < NSEQ / 2; i += blockDim.x) acc |= w[2 * i + 1];
    if (acc) atomicOr(&any, 1);
    __syncthreads();
    if (threadIdx.x == 0) g_is64 = (any == 0) ? 1 : 0;
}

// ---------------- embedding gather ----------------
__global__ void gather_kernel(const void* __restrict__ nums, const float* __restrict__ emb) {
    int t = blockIdx.x;
    long long idx = g_is64 ? ((const long long*)nums)[t]
                           : (long long)((const int*)nums)[t];
    const float4* src = (const float4*)(emb + (size_t)idx * DD);
    float4* dst = (float4*)(&g_X[(size_t)t * DD]);
    int i = threadIdx.x;              // blockDim = 128 == DD/4
    dst[i] = src[i];
}

// ---------------- SIMT tiled SGEMM: C[2048,512] = A@B + bias ----------------
__global__ __launch_bounds__(256)
void gemm_bias(const float* __restrict__ A, const float* __restrict__ B,
               const float* __restrict__ bias, float* __restrict__ C)
{
    __shared__ __align__(16) float As[16][68];
    __shared__ __align__(16) float Bs[16][68];
    const int tid = threadIdx.x;
    const int bm = blockIdx.y * 64;
    const int bn = blockIdx.x * 64;
    const int tm = tid >> 4, tn = tid & 15;
    float acc[4][4] = {};
    for (int k0 = 0; k0 < 512; k0 += 16) {
        {
            int row = tid >> 2, cg = (tid & 3) * 4;
            float4 v = *(const float4*)(A + (size_t)(bm + row) * 512 + k0 + cg);
            As[cg + 0][row] = v.x; As[cg + 1][row] = v.y;
            As[cg + 2][row] = v.z; As[cg + 3][row] = v.w;
        }
        {
            int row = tid >> 4, col = (tid & 15) * 4;
            *(float4*)&Bs[row][col] = *(const float4*)(B + (size_t)(k0 + row) * 512 + bn + col);
        }
        __syncthreads();
#pragma unroll
        for (int k = 0; k < 16; k++) {
            float4 a = *(const float4*)&As[k][tm * 4];
            float4 b = *(const float4*)&Bs[k][tn * 4];
            float av[4] = {a.x, a.y, a.z, a.w};
            float bv[4] = {b.x, b.y, b.z, b.w};
#pragma unroll
            for (int i = 0; i < 4; i++)
#pragma unroll
                for (int jj = 0; jj < 4; jj++)
                    acc[i][jj] = fmaf(av[i], bv[jj], acc[i][jj]);
        }
        __syncthreads();
    }
    float4 bb = *(const float4*)(bias + bn + tn * 4);
#pragma unroll
    for (int i = 0; i < 4; i++) {
        float4 o;
        o.x = acc[i][0] + bb.x; o.y = acc[i][1] + bb.y;
        o.z = acc[i][2] + bb.z; o.w = acc[i][3] + bb.w;
        *(float4*)(C + (size_t)(bm + tm * 4 + i) * 512 + bn + tn * 4) = o;
    }
}

// h/c state layout in smem: 32 groups of 16 values, group stride 20 words
// (16B-aligned; lane s reads words [s*20, s*20+16) as 4x LDS.128 — the 8-lane
// phase covers all 32 banks conflict-free). Two buffers of 640 words.
#define GSTRIDE 20
#define BUFW    640

// ---------------- RNN recurrence: 16-CTA cluster ----------------
// CTA rank owns outputs j in [rank*32, rank*32+32). Warp w handles j0=rank*32+w
// and j1=j0+16. Lane s owns k-slice [s*16, s*16+16) with weights in registers.
__global__ void __launch_bounds__(512, 1)
rnn16(const float* __restrict__ Whh, const float* __restrict__ XW,
      float* __restrict__ Hout)
{
    __shared__ __align__(16) float sh[2 * BUFW];
    const int tid  = threadIdx.x;
    const int lane = tid & 31;
    const int w    = tid >> 5;
    const uint32_t rank = ctarank();
    const int j0 = (int)rank * 32 + w;
    const int j1 = j0 + 16;

    float w0[16], w1[16];
#pragma unroll
    for (int i = 0; i < 16; i++) {
        w0[i] = Whh[(size_t)(lane * 16 + i) * DD + j0];
        w1[i] = Whh[(size_t)(lane * 16 + i) * DD + j1];
    }
    for (int i = tid; i < 2 * BUFW; i += 512) sh[i] = 0.0f;   // h0 = 0
    __syncthreads();
    const uint32_t base = s2u(sh);

    float xw0 = XW[j0], xw1 = XW[j1];   // prefetch t = 0
    cl_arrive();

#pragma unroll 1
    for (int t = 0; t < NSEQ; t++) {
        cl_wait();
        const float* cb = sh + (t & 1) * BUFW + lane * GSTRIDE;
        float hv[16];
        *(float4*)&hv[0]  = *(const float4*)(cb);
        *(float4*)&hv[4]  = *(const float4*)(cb + 4);
        *(float4*)&hv[8]  = *(const float4*)(cb + 8);
        *(float4*)&hv[12] = *(const float4*)(cb + 12);

        float pa = 0, pb = 0, qa = 0, qb = 0;
#pragma unroll
        for (int i = 0; i < 16; i += 2) {
            pa = fmaf(hv[i],     w0[i],     pa);
            pb = fmaf(hv[i + 1], w0[i + 1], pb);
            qa = fmaf(hv[i],     w1[i],     qa);
            qb = fmaf(hv[i + 1], w1[i + 1], qb);
        }
        float p = pa + pb, q = qa + qb;
#pragma unroll
        for (int off = 16; off; off >>= 1) {
            p += __shfl_xor_sync(0xffffffffu, p, off);
            q += __shfl_xor_sync(0xffffffffu, q, off);
        }
        float h0 = tanh_ex2(xw0 + p);
        float h1 = tanh_ex2(xw1 + q);
        if (lane == 0) {
            Hout[(size_t)t * DD + j0] = h0;
            Hout[(size_t)t * DD + j1] = h1;
        }
        {   // lanes 0..15 each deliver both values to CTA == lane
            const int nb = 1 - (t & 1);
            if (lane < CL) {
                uint32_t ad = base + 4u * (uint32_t)(nb * BUFW + (int)rank * (2 * GSTRIDE) + w);
                dsmem_st(ad,                 (uint32_t)lane, h0);
                dsmem_st(ad + 4u * GSTRIDE,  (uint32_t)lane, h1);
            }
        }
        cl_arrive();
        if (t + 1 < NSEQ) {   // prefetch hidden under the barrier
            xw0 = XW[(size_t)(t + 1) * DD + j0];
            xw1 = XW[(size_t)(t + 1) * DD + j1];
        }
    }
    cl_wait();
}

// ---------------- CRF backward logsumexp: 16-CTA cluster ----------------
// State stored pre-scaled by log2(e). Max computed consumer-side from the
// registers every warp loads anyway (covers all 512 v in one warp).
__global__ void __launch_bounds__(512, 1)
crf16(const float* __restrict__ T, const float* __restrict__ O,
      float* __restrict__ out)
{
    __shared__ __align__(16) float sh[2 * BUFW];
    const int tid  = threadIdx.x;
    const int lane = tid & 31;
    const int w    = tid >> 5;
    const uint32_t rank = ctarank();
    const int u0 = (int)rank * 32 + w;
    const int u1 = u0 + 16;
    const float L2E = 1.4426950408889634f;
    const float LN2 = 0.6931471805599453f;

    float t0[16], t1[16];
#pragma unroll
    for (int i = 0; i < 16; i++) {
        t0[i] = T[(size_t)u0 * VV + lane * 16 + i] * L2E;
        t1[i] = T[(size_t)u1 * VV + lane * 16 + i] * L2E;
    }
    for (int i = tid; i < 2 * BUFW; i += 512) sh[i] = -1.0e30f;
    __syncthreads();
    if (tid == 0) sh[1] = O[(size_t)(NSEQ - 1) * VV + 1] * L2E;  // c_init[EOS], buf0 grp0 word1
    __syncthreads();
    const uint32_t base = s2u(sh);

    float o0 = O[(size_t)(NSEQ - 2) * VV + u0];   // prefetch si = 0
    float o1 = O[(size_t)(NSEQ - 2) * VV + u1];
    cl_arrive();

#pragma unroll 1
    for (int si = 0; si < NSEQ - 1; si++) {
        cl_wait();
        const float* cb = sh + (si & 1) * BUFW + lane * GSTRIDE;
        float cv[16];
        *(float4*)&cv[0]  = *(const float4*)(cb);
        *(float4*)&cv[4]  = *(const float4*)(cb + 4);
        *(float4*)&cv[8]  = *(const float4*)(cb + 8);
        *(float4*)&cv[12] = *(const float4*)(cb + 12);

        // global max of c (in log2e units): per-lane slice max, then butterfly
        float m0 = fmaxf(cv[0], cv[1]),   m1 = fmaxf(cv[2], cv[3]);
        float m2 = fmaxf(cv[4], cv[5]),   m3 = fmaxf(cv[6], cv[7]);
        float m4 = fmaxf(cv[8], cv[9]),   m5 = fmaxf(cv[10], cv[11]);
        float m6 = fmaxf(cv[12], cv[13]), m7 = fmaxf(cv[14], cv[15]);
        float mx = fmaxf(fmaxf(fmaxf(m0, m1), fmaxf(m2, m3)),
                         fmaxf(fmaxf(m4, m5), fmaxf(m6, m7)));
#pragma unroll
        for (int off = 16; off; off >>= 1)
            mx = fmaxf(mx, __shfl_xor_sync(0xffffffffu, mx, off));

        float s0a = 0, s0b = 0, s1a = 0, s1b = 0;
#pragma unroll
        for (int i = 0; i < 16; i += 2) {
            s0a += ex2f_(cv[i]     + t0[i]     - mx);
            s0b += ex2f_(cv[i + 1] + t0[i + 1] - mx);
            s1a += ex2f_(cv[i]     + t1[i]     - mx);
            s1b += ex2f_(cv[i + 1] + t1[i + 1] - mx);
        }
        float s0 = s0a + s0b, s1 = s1a + s1b;
#pragma unroll
        for (int off = 16; off; off >>= 1) {
            s0 += __shfl_xor_sync(0xffffffffu, s0, off);
            s1 += __shfl_xor_sync(0xffffffffu, s1, off);
        }
        float cn0 = o0 + (mx + lg2f_(s0)) * LN2;
        float cn1 = o1 + (mx + lg2f_(s1)) * LN2;

        if (si == NSEQ - 2) {
            if (rank == 0 && w == 0 && lane == 0) out[0] = cn0;  // c0[BOS]
        } else {
            const int nb = 1 - (si & 1);
            if (lane < CL) {
                uint32_t ad = base + 4u * (uint32_t)(nb * BUFW + (int)rank * (2 * GSTRIDE) + w);
                dsmem_st(ad,                (uint32_t)lane, cn0 * L2E);
                dsmem_st(ad + 4u * GSTRIDE, (uint32_t)lane, cn1 * L2E);
            }
        }
        cl_arrive();
        if (si + 1 < NSEQ - 1) {   // prefetch next row under the barrier
            int row = NSEQ - 3 - si;
            o0 = O[(size_t)row * VV + u0];
            o1 = O[(size_t)row * VV + u1];
        }
    }
    cl_wait();
}

// ---------------- launch ----------------
extern "C" void kernel_launch(void* const* d_in, const int* in_sizes, int n_in,
                              void* d_out, int out_size)
{
    const void*  nums = d_in[0];
    const float* emb  = (const float*)d_in[1];
    const float* Wxh1 = (const float*)d_in[2];
    const float* Whh1 = (const float*)d_in[3];
    const float* b1   = (const float*)d_in[4];
    const float* Wxh2 = (const float*)d_in[5];
    const float* Whh2 = (const float*)d_in[6];
    const float* b2   = (const float*)d_in[7];
    const float* Wl   = (const float*)d_in[8];
    const float* bl   = (const float*)d_in[9];
    const float* Tm   = (const float*)d_in[10];
    float* out = (float*)d_out;

    float *X, *XW, *H, *O;
    cudaGetSymbolAddress((void**)&X,  g_X);
    cudaGetSymbolAddress((void**)&XW, g_XW);
    cudaGetSymbolAddress((void**)&H,  g_H);
    cudaGetSymbolAddress((void**)&O,  g_O);

    // nonportable cluster size 16 (idempotent; host-side, capture-safe)
    cudaFuncSetAttribute((const void*)rnn16, cudaFuncAttributeNonPortableClusterSizeAllowed, 1);
    cudaFuncSetAttribute((const void*)crf16, cudaFuncAttributeNonPortableClusterSizeAllowed, 1);

    detect_kernel<<<1, 256>>>((const int*)nums);
    gather_kernel<<<NSEQ, 128>>>(nums, emb);

    dim3 gg(512 / 64, NSEQ / 64);
    gemm_bias<<<gg, 256>>>(X, Wxh1, b1, XW);      // XW1 = X@Wxh1 + b1

    cudaLaunchConfig_t cfg = {};
    cfg.gridDim  = dim3(CL, 1, 1);
    cfg.blockDim = dim3(512, 1, 1);
    cfg.dynamicSmemBytes = 0;
    cfg.stream = 0;
    cudaLaunchAttribute at[1];
    at[0].id = cudaLaunchAttributeClusterDimension;
    at[0].val.clusterDim.x = CL;
    at[0].val.clusterDim.y = 1;
    at[0].val.clusterDim.z = 1;
    cfg.attrs = at;
    cfg.numAttrs = 1;

    cudaLaunchKernelEx(&cfg, rnn16, (const float*)Whh1, (const float*)XW, H);   // G
    gemm_bias<<<gg, 256>>>(H, Wxh2, b2, XW);      // XW2 = G@Wxh2 + b2
    cudaLaunchKernelEx(&cfg, rnn16, (const float*)Whh2, (const float*)XW, H);   // H
    gemm_bias<<<gg, 256>>>(H, Wl, bl, O);         // O = H@Wl + bl
    cudaLaunchKernelEx(&cfg, crf16, (const float*)Tm, (const float*)O, out);    // c0[BOS]
}

// round 3
// speedup vs baseline: 1.9690x; 1.9690x over previous
#include <cuda_runtime.h>
#include <cstdint>

#define NSEQ 2048
#define DD 512
#define VV 512
#define CL 16
#define GSTRIDE 20
#define BUFW 640          // 32 groups * GSTRIDE

// ---------------- device scratch ----------------
static __device__ float g_X [NSEQ * DD];
static __device__ float g_XW[NSEQ * DD];
static __device__ float g_H [NSEQ * DD];
static __device__ float g_O [NSEQ * VV];
static __device__ float g_E [VV * VV];
static __device__ int   g_is64;

// ---------------- helpers ----------------
__device__ __forceinline__ uint32_t ctarank() {
    uint32_t r; asm("mov.u32 %0, %%cluster_ctarank;" : "=r"(r)); return r;
}
__device__ __forceinline__ uint32_t s2u(const void* p) {
    uint32_t a;
    asm("{ .reg .u64 t; cvta.to.shared.u64 t, %1; cvt.u32.u64 %0, t; }" : "=r"(a) : "l"(p));
    return a;
}
__device__ __forceinline__ uint32_t mapa_(uint32_t laddr, uint32_t r) {
    uint32_t a; asm("mapa.shared::cluster.u32 %0, %1, %2;" : "=r"(a) : "r"(laddr), "r"(r));
    return a;
}
__device__ __forceinline__ void st_async64(uint32_t raddr, uint64_t v, uint32_t rmbar) {
    asm volatile("st.async.shared::cluster.mbarrier::complete_tx::bytes.b64 [%0], %1, [%2];"
                 :: "r"(raddr), "l"(v), "r"(rmbar) : "memory");
}
__device__ __forceinline__ void mbar_init(uint32_t mb, uint32_t cnt) {
    asm volatile("mbarrier.init.shared.b64 [%0], %1;" :: "r"(mb), "r"(cnt) : "memory");
}
__device__ __forceinline__ void mbar_expect(uint32_t mb, uint32_t bytes) {
    asm volatile("mbarrier.arrive.expect_tx.shared.b64 _, [%0], %1;" :: "r"(mb), "r"(bytes) : "memory");
}
__device__ __forceinline__ void mbar_wait(uint32_t mb, uint32_t parity) {
    asm volatile(
        "{\n\t.reg .pred P;\n"
        "W%=:\n\t"
        "mbarrier.try_wait.parity.acquire.cluster.shared::cta.b64 P, [%0], %1, 0x989680;\n\t"
        "@!P bra W%=;\n\t}"
        :: "r"(mb), "r"(parity) : "memory");
}
__device__ __forceinline__ void cl_sync() {
    asm volatile("barrier.cluster.arrive.aligned;" ::: "memory");
    asm volatile("barrier.cluster.wait.aligned;"   ::: "memory");
}
__device__ __forceinline__ float ex2f_(float x) {
    float y; asm("ex2.approx.f32 %0, %1;" : "=f"(y) : "f"(x)); return y;
}
__device__ __forceinline__ float lg2f_(float x) {
    float y; asm("lg2.approx.f32 %0, %1;" : "=f"(y) : "f"(x)); return y;
}
__device__ __forceinline__ float rcpf_(float x) {
    float y; asm("rcp.approx.f32 %0, %1;" : "=f"(y) : "f"(x)); return y;
}
__device__ __forceinline__ float tanh_ex2(float x) {     // 1 - 2/(e^2x+1)
    float t = ex2f_(2.8853900817779268f * x);
    float r = rcpf_(t + 1.0f);
    return fmaf(-2.0f, r, 1.0f);
}
__device__ __forceinline__ uint64_t pack2(float a, float b) {
    return (uint64_t)__float_as_uint(a) | ((uint64_t)__float_as_uint(b) << 32);
}

// ---------------- int64-vs-int32 index detection ----------------
__global__ void detect_kernel(const int* __restrict__ w) {
    __shared__ int any;
    if (threadIdx.x == 0) any = 0;
    __syncthreads();
    int acc = 0;
    for (int i = threadIdx.x; i < NSEQ / 2; i += blockDim.x) acc |= w[2 * i + 1];
    if (acc) atomicOr(&any, 1);
    __syncthreads();
    if (threadIdx.x == 0) g_is64 = (any == 0) ? 1 : 0;
}

// ---------------- embedding gather ----------------
__global__ void gather_kernel(const void* __restrict__ nums, const float* __restrict__ emb) {
    int t = blockIdx.x;
    long long idx = g_is64 ? ((const long long*)nums)[t]
                           : (long long)((const int*)nums)[t];
    const float4* src = (const float4*)(emb + (size_t)idx * DD);
    float4* dst = (float4*)(&g_X[(size_t)t * DD]);
    dst[threadIdx.x] = src[threadIdx.x];      // blockDim = 128
}

// ---------------- precompute E = exp(T) (base-2 weights) ----------------
__global__ void expT_kernel(const float* __restrict__ T) {
    int i = blockIdx.x * 256 + threadIdx.x;
    g_E[i] = ex2f_(T[i] * 1.4426950408889634f);
}

// ---------------- SIMT tiled SGEMM: C[2048,512] = A@B + bias ----------------
__global__ __launch_bounds__(256)
void gemm_bias(const float* __restrict__ A, const float* __restrict__ B,
               const float* __restrict__ bias, float* __restrict__ C)
{
    __shared__ __align__(16) float As[16][68];
    __shared__ __align__(16) float Bs[16][68];
    const int tid = threadIdx.x;
    const int bm = blockIdx.y * 64;
    const int bn = blockIdx.x * 64;
    const int tm = tid >> 4, tn = tid & 15;
    float acc[4][4] = {};
    for (int k0 = 0; k0 < 512; k0 += 16) {
        {
            int row = tid >> 2, cg = (tid & 3) * 4;
            float4 v = *(const float4*)(A + (size_t)(bm + row) * 512 + k0 + cg);
            As[cg + 0][row] = v.x; As[cg + 1][row] = v.y;
            As[cg + 2][row] = v.z; As[cg + 3][row] = v.w;
        }
        {
            int row = tid >> 4, col = (tid & 15) * 4;
            *(float4*)&Bs[row][col] = *(const float4*)(B + (size_t)(k0 + row) * 512 + bn + col);
        }
        __syncthreads();
#pragma unroll
        for (int k = 0; k < 16; k++) {
            float4 a = *(const float4*)&As[k][tm * 4];
            float4 b = *(const float4*)&Bs[k][tn * 4];
            float av[4] = {a.x, a.y, a.z, a.w};
            float bv[4] = {b.x, b.y, b.z, b.w};
#pragma unroll
            for (int i = 0; i < 4; i++)
#pragma unroll
                for (int jj = 0; jj < 4; jj++)
                    acc[i][jj] = fmaf(av[i], bv[jj], acc[i][jj]);
        }
        __syncthreads();
    }
    float4 bb = *(const float4*)(bias + bn + tn * 4);
#pragma unroll
    for (int i = 0; i < 4; i++) {
        float4 o;
        o.x = acc[i][0] + bb.x; o.y = acc[i][1] + bb.y;
        o.z = acc[i][2] + bb.z; o.w = acc[i][3] + bb.w;
        *(float4*)(C + (size_t)(bm + tm * 4 + i) * 512 + bn + tn * 4) = o;
    }
}

// Value j lives at word (j>>4)*GSTRIDE + (j&15) within a buffer.
// Warp w of CTA rank owns adjacent outputs j0 = rank*32 + 2w, j1 = j0+1
// (8B-aligned pair -> one st.async.b64 per target CTA, sent by lanes 0..15).

// ---------------- RNN recurrence: dataflow-synced 16-CTA cluster ----------------
__global__ void __launch_bounds__(512, 1)
rnn16(const float* __restrict__ Whh, const float* __restrict__ XW,
      float* __restrict__ Hout)
{
    __shared__ __align__(16) float sh[2 * BUFW];
    __shared__ __align__(8) long long mbar[2];
    const int tid  = threadIdx.x;
    const int lane = tid & 31;
    const int w    = tid >> 5;
    const uint32_t rank = ctarank();
    const int j0 = (int)rank * 32 + 2 * w;

    float w0[16], w1[16];
#pragma unroll
    for (int i = 0; i < 16; i++) {
        w0[i] = Whh[(size_t)(lane * 16 + i) * DD + j0];
        w1[i] = Whh[(size_t)(lane * 16 + i) * DD + j0 + 1];
    }
    for (int i = tid; i < 2 * BUFW; i += 512) sh[i] = 0.0f;   // h0 = 0

    const uint32_t base = s2u(sh);
    const uint32_t mb0  = s2u(&mbar[0]);
    if (tid == 0) {
        mbar_init(mb0, 1);     mbar_init(mb0 + 8, 1);
        mbar_expect(mb0, 2048); mbar_expect(mb0 + 8, 2048);   // arm t=2 / t=1
    }
    __syncthreads();
    cl_sync();   // all mbarriers armed before any remote store

    // remote store targets (lane < CL): target CTA == lane
    uint32_t rA0 = 0, rM0 = 0;
    const uint32_t off0 = (uint32_t)(((rank * 2 + (w >> 3)) * GSTRIDE + (w & 7) * 2) * 4);
    if (lane < CL) {
        rA0 = mapa_(base + off0, (uint32_t)lane);
        rM0 = mapa_(mb0, (uint32_t)lane);
    }

    float2 xw = *(const float2*)&XW[j0];   // prefetch t = 0

#pragma unroll 1
    for (int t = 0; t < NSEQ; t++) {
        const uint32_t p = (uint32_t)(t & 1);
        if (t) {
            mbar_wait(mb0 + 8 * p, (uint32_t)(((t - 1) >> 1) & 1));
            if (tid == 0) mbar_expect(mb0 + 8 * p, 2048);      // re-arm for t+2
        }
        const float* cb = sh + p * BUFW + lane * GSTRIDE;
        float hv[16];
        *(float4*)&hv[0]  = *(const float4*)(cb);
        *(float4*)&hv[4]  = *(const float4*)(cb + 4);
        *(float4*)&hv[8]  = *(const float4*)(cb + 8);
        *(float4*)&hv[12] = *(const float4*)(cb + 12);

        float pa = 0, pb = 0, qa = 0, qb = 0;
#pragma unroll
        for (int i = 0; i < 16; i += 2) {
            pa = fmaf(hv[i],     w0[i],     pa);
            pb = fmaf(hv[i + 1], w0[i + 1], pb);
            qa = fmaf(hv[i],     w1[i],     qa);
            qb = fmaf(hv[i + 1], w1[i + 1], qb);
        }
        float pp = pa + pb, qq = qa + qb;
#pragma unroll
        for (int o = 16; o; o >>= 1) {
            pp += __shfl_xor_sync(0xffffffffu, pp, o);
            qq += __shfl_xor_sync(0xffffffffu, qq, o);
        }
        float h0 = tanh_ex2(xw.x + pp);
        float h1 = tanh_ex2(xw.y + qq);
        if (lane == 0) *(float2*)&Hout[(size_t)t * DD + j0] = make_float2(h0, h1);

        if (t + 1 < NSEQ) {
            if (lane < CL) {
                const uint32_t np = (uint32_t)((t + 1) & 1);
                st_async64(rA0 + np * (BUFW * 4), pack2(h0, h1), rM0 + 8 * np);
            }
            xw = *(const float2*)&XW[(size_t)(t + 1) * DD + j0];   // prefetch
        }
    }
    cl_sync();
}

// ---------------- CRF backward: dataflow-synced, exp(T)-factored ----------------
// State c kept in log2 units. Per step: e[v] = exp2(c[v] - c[EOS]) (1 ex2/thread,
// shared via SMEM), then s_u = sum_v E[u,v] * e[v] (pure FMA matvec),
// c_new[u] = o[u]*log2e + c[EOS] + log2(s_u).
__global__ void __launch_bounds__(512, 1)
crf16(const float* __restrict__ O, float* __restrict__ out)
{
    __shared__ __align__(16) float sh[2 * BUFW];
    __shared__ __align__(16) float eb[2 * BUFW];
    __shared__ __align__(8) long long mbar[2];
    const int tid  = threadIdx.x;
    const int lane = tid & 31;
    const int w    = tid >> 5;
    const uint32_t rank = ctarank();
    const int u0 = (int)rank * 32 + 2 * w;
    const float L2E = 1.4426950408889634f;
    const float LN2 = 0.6931471805599453f;

    float e0[16], e1[16];
#pragma unroll
    for (int i = 0; i < 16; i++) {
        e0[i] = g_E[(size_t)u0 * VV + lane * 16 + i];
        e1[i] = g_E[(size_t)(u0 + 1) * VV + lane * 16 + i];
    }
    for (int i = tid; i < 2 * BUFW; i += 512) sh[i] = -1.0e30f;

    const uint32_t base = s2u(sh);
    const uint32_t mb0  = s2u(&mbar[0]);
    if (tid == 0) {
        sh[1] = O[(size_t)(NSEQ - 1) * VV + 1] * L2E;   // c_init[EOS], buf0 word 1
        mbar_init(mb0, 1);     mbar_init(mb0 + 8, 1);
        mbar_expect(mb0, 2048); mbar_expect(mb0 + 8, 2048);
    }
    __syncthreads();
    cl_sync();

    uint32_t rA0 = 0, rM0 = 0;
    const uint32_t off0 = (uint32_t)(((rank * 2 + (w >> 3)) * GSTRIDE + (w & 7) * 2) * 4);
    if (lane < CL) {
        rA0 = mapa_(base + off0, (uint32_t)lane);
        rM0 = mapa_(mb0, (uint32_t)lane);
    }
    const int myword = (tid >> 4) * GSTRIDE + (tid & 15);   // c[tid] location

    float2 ov = *(const float2*)&O[(size_t)(NSEQ - 2) * VV + u0];   // prefetch si=0
    float o0 = ov.x * L2E, o1 = ov.y * L2E;

#pragma unroll 1
    for (int si = 0; si < NSEQ - 1; si++) {
        const uint32_t p = (uint32_t)(si & 1);
        if (si) {
            mbar_wait(mb0 + 8 * p, (uint32_t)(((si - 1) >> 1) & 1));
            if (tid == 0) mbar_expect(mb0 + 8 * p, 2048);
        }
        const float* cbuf = sh + p * BUFW;
        const float offc = cbuf[1];                    // c[EOS] (log2 units)
        const float ev = ex2f_(cbuf[myword] - offc);   // e[tid]
        float* ebuf = eb + p * BUFW;
        ebuf[myword] = ev;
        __syncthreads();

        const float* ep = ebuf + lane * GSTRIDE;
        float x0, x1, x2, x3;
        float s0a = 0, s0b = 0, s1a = 0, s1b = 0;
        float exv[16];
        *(float4*)&exv[0]  = *(const float4*)(ep);
        *(float4*)&exv[4]  = *(const float4*)(ep + 4);
        *(float4*)&exv[8]  = *(const float4*)(ep + 8);
        *(float4*)&exv[12] = *(const float4*)(ep + 12);
        (void)x0; (void)x1; (void)x2; (void)x3;
#pragma unroll
        for (int i = 0; i < 16; i += 2) {
            s0a = fmaf(exv[i],     e0[i],     s0a);
            s0b = fmaf(exv[i + 1], e0[i + 1], s0b);
            s1a = fmaf(exv[i],     e1[i],     s1a);
            s1b = fmaf(exv[i + 1], e1[i + 1], s1b);
        }
        float s0 = s0a + s0b, s1 = s1a + s1b;
#pragma unroll
        for (int o = 16; o; o >>= 1) {
            s0 += __shfl_xor_sync(0xffffffffu, s0, o);
            s1 += __shfl_xor_sync(0xffffffffu, s1, o);
        }
        float cl0 = o0 + offc + lg2f_(s0);
        float cl1 = o1 + offc + lg2f_(s1);

        if (si == NSEQ - 2) {
            if (rank == 0 && w == 0 && lane == 0) out[0] = cl0 * LN2;   // c0[BOS]
        } else {
            if (lane < CL) {
                const uint32_t np = (uint32_t)((si + 1) & 1);
                st_async64(rA0 + np * (BUFW * 4), pack2(cl0, cl1), rM0 + 8 * np);
            }
            int row = NSEQ - 3 - si;                    // prefetch next o
            float2 onx = *(const float2*)&O[(size_t)row * VV + u0];
            o0 = onx.x * L2E; o1 = onx.y * L2E;
        }
    }
    cl_sync();
}

// ---------------- launch ----------------
extern "C" void kernel_launch(void* const* d_in, const int* in_sizes, int n_in,
                              void* d_out, int out_size)
{
    const void*  nums = d_in[0];
    const float* emb  = (const float*)d_in[1];
    const float* Wxh1 = (const float*)d_in[2];
    const float* Whh1 = (const float*)d_in[3];
    const float* b1   = (const float*)d_in[4];
    const float* Wxh2 = (const float*)d_in[5];
    const float* Whh2 = (const float*)d_in[6];
    const float* b2   = (const float*)d_in[7];
    const float* Wl   = (const float*)d_in[8];
    const float* bl   = (const float*)d_in[9];
    const float* Tm   = (const float*)d_in[10];
    float* out = (float*)d_out;

    float *X, *XW, *H, *O;
    cudaGetSymbolAddress((void**)&X,  g_X);
    cudaGetSymbolAddress((void**)&XW, g_XW);
    cudaGetSymbolAddress((void**)&H,  g_H);
    cudaGetSymbolAddress((void**)&O,  g_O);

    cudaFuncSetAttribute((const void*)rnn16, cudaFuncAttributeNonPortableClusterSizeAllowed, 1);
    cudaFuncSetAttribute((const void*)crf16, cudaFuncAttributeNonPortableClusterSizeAllowed, 1);

    detect_kernel<<<1, 256>>>((const int*)nums);
    gather_kernel<<<NSEQ, 128>>>(nums, emb);
    expT_kernel<<<VV * VV / 256, 256>>>(Tm);

    dim3 gg(512 / 64, NSEQ / 64);
    gemm_bias<<<gg, 256>>>(X, Wxh1, b1, XW);

    cudaLaunchConfig_t cfg = {};
    cfg.gridDim  = dim3(CL, 1, 1);
    cfg.blockDim = dim3(512, 1, 1);
    cfg.dynamicSmemBytes = 0;
    cfg.stream = 0;
    cudaLaunchAttribute at[1];
    at[0].id = cudaLaunchAttributeClusterDimension;
    at[0].val.clusterDim.x = CL;
    at[0].val.clusterDim.y = 1;
    at[0].val.clusterDim.z = 1;
    cfg.attrs = at;
    cfg.numAttrs = 1;

    cudaLaunchKernelEx(&cfg, rnn16, (const float*)Whh1, (const float*)XW, H);
    gemm_bias<<<gg, 256>>>(H, Wxh2, b2, XW);
    cudaLaunchKernelEx(&cfg, rnn16, (const float*)Whh2, (const float*)XW, H);
    gemm_bias<<<gg, 256>>>(H, Wl, bl, O);
    cudaLaunchKernelEx(&cfg, crf16, (const float*)O, out);
}